// round 5
// baseline (speedup 1.0000x reference)
#include <cuda_runtime.h>
#include <cuda_bf16.h>
#include <math.h>

#define HW 200704
#define CC 192
#define NHEAD 6

// ---------------- scratch ----------------
__device__ float g_mu[HW];
__device__ float g_rstd[HW];
__device__ float g_Wf[576 * CC];
__device__ float g_bias[576];
__device__ float g_G[CC * CC];
__device__ float g_s[CC];
__device__ float g_T[384 * CC];
__device__ float g_u[384];
__device__ __align__(16) __nv_bfloat16 g_Wvb[CC * CC];   // v rows of folded weight, bf16
__device__ __align__(16) __nv_bfloat16 g_Wpb[CC * CC];   // proj_w bf16
__device__ __align__(16) __nv_bfloat16 g_gmc[CC * 32];   // per-head gm blocks, compact [192][32]

// ---------------- mma helper ----------------
__device__ __forceinline__ void mma16816(float* c, const unsigned* a, const unsigned* b) {
    asm volatile(
        "mma.sync.aligned.m16n8k16.row.col.f32.bf16.bf16.f32 "
        "{%0,%1,%2,%3},{%4,%5,%6,%7},{%8,%9},{%0,%1,%2,%3};\n"
        : "+f"(c[0]), "+f"(c[1]), "+f"(c[2]), "+f"(c[3])
        : "r"(a[0]), "r"(a[1]), "r"(a[2]), "r"(a[3]), "r"(b[0]), "r"(b[1]));
}

__device__ __forceinline__ float redmax(float v) {
#pragma unroll
    for (int m = 4; m <= 16; m <<= 1) v = fmaxf(v, __shfl_xor_sync(0xffffffffu, v, m));
    return v;
}
__device__ __forceinline__ float redsum(float v) {
#pragma unroll
    for (int m = 4; m <= 16; m <<= 1) v += __shfl_xor_sync(0xffffffffu, v, m);
    return v;
}

// ---------------- zero accumulators ----------------
__global__ void k_zero() {
    int i = blockIdx.x * 256 + threadIdx.x;
    if (i < CC * CC) g_G[i] = 0.f;
    if (i < CC) g_s[i] = 0.f;
}

// ---------------- per-pixel LN stats ----------------
__global__ void k_stats(const float* __restrict__ x) {
    int p = blockIdx.x * 256 + threadIdx.x;
    float s = 0.f, ss = 0.f;
#pragma unroll 8
    for (int c = 0; c < CC; c++) {
        float v = x[c * HW + p];
        s += v; ss += v * v;
    }
    float mu  = s * (1.f / CC);
    float var = ss * (1.f / CC) - mu * mu;
    g_mu[p]   = mu;
    g_rstd[p] = rsqrtf(var + 1e-5f);
}

// ---------------- fold weights ----------------
__global__ void k_fold(const float* __restrict__ qkv_w, const float* __restrict__ pre_w,
                       const float* __restrict__ ln_g, const float* __restrict__ ln_b,
                       const float* __restrict__ pre_b) {
    int o = blockIdx.x, j = threadIdx.x;
    float w2 = 0.f;
#pragma unroll 4
    for (int c = 0; c < CC; c++) w2 += qkv_w[o * CC + c] * pre_w[c * CC + j];
    float wf = w2 * ln_g[j];
    g_Wf[o * CC + j] = wf;
    if (o >= 384) g_Wvb[(o - 384) * CC + j] = __float2bfloat16(wf);
    __shared__ float s2[CC];
    s2[j] = w2 * ln_b[j] + qkv_w[o * CC + j] * pre_b[j];
    __syncthreads();
    if (j < 64) s2[j] += s2[j + 64] + s2[j + 128];
    __syncthreads();
    if (j < 32) {
        float b = s2[j] + s2[j + 32];
#pragma unroll
        for (int off = 16; off > 0; off >>= 1) b += __shfl_down_sync(0xffffffffu, b, off);
        if (j == 0) g_bias[o] = b;
    }
}

__global__ void k_cvt(const float* __restrict__ w) {
    int i = blockIdx.x * 256 + threadIdx.x;
    if (i < CC * CC) g_Wpb[i] = __float2bfloat16(w[i]);
}

// ---------------- Gram of xhat: persistent, full 192x192 per block ----------------
#define NT (HW / 32)
__global__ __launch_bounds__(256) void k_gram(const float* __restrict__ x) {
    __shared__ __align__(16) unsigned short xs[2][CC][40];
    int tid = threadIdx.x;
    int warp = tid >> 5, lane = tid & 31, gid = lane >> 2, tig = lane & 3;
    int m0 = (warp & 3) * 48;
    int n0 = (warp >> 2) * 96;
    float acc[3][12][4];
#pragma unroll
    for (int f = 0; f < 3; f++)
#pragma unroll
        for (int g = 0; g < 12; g++)
#pragma unroll
            for (int r = 0; r < 4; r++) acc[f][g][r] = 0.f;
    float srow[12];
#pragma unroll
    for (int i = 0; i < 12; i++) srow[i] = 0.f;

    auto load_tile = [&](int t, int b) {
        int p0 = t * 32;
#pragma unroll
        for (int i = 0; i < 12; i++) {
            int q = tid + 256 * i;
            int c = q >> 4, pp = q & 15;
            int p = p0 + pp * 2;
            float2 xv = *(const float2*)(x + c * HW + p);
            float2 m2 = *(const float2*)(g_mu + p);
            float2 r2 = *(const float2*)(g_rstd + p);
            float h0 = (xv.x - m2.x) * r2.x;
            float h1 = (xv.y - m2.y) * r2.y;
            __nv_bfloat162 bb = __floats2bfloat162_rn(h0, h1);
            *(unsigned*)&xs[b][c][pp * 2] = *(unsigned*)&bb;
            srow[i] += h0 + h1;
        }
    };

    int t = blockIdx.x;
    int iter = 0;
    if (t < NT) {
        load_tile(t, 0);
        __syncthreads();
        while (t < NT) {
            int b = iter & 1;
            int tn = t + gridDim.x;
            if (tn < NT) load_tile(tn, b ^ 1);
#pragma unroll
            for (int ks = 0; ks < 2; ks++) {
                int kl = ks * 16 + 2 * tig;
                unsigned a[3][4];
#pragma unroll
                for (int f = 0; f < 3; f++) {
                    int r = m0 + f * 16 + gid;
                    a[f][0] = *(const unsigned*)&xs[b][r][kl];
                    a[f][1] = *(const unsigned*)&xs[b][r + 8][kl];
                    a[f][2] = *(const unsigned*)&xs[b][r][kl + 8];
                    a[f][3] = *(const unsigned*)&xs[b][r + 8][kl + 8];
                }
#pragma unroll
                for (int g = 0; g < 12; g++) {
                    int n = n0 + g * 8 + gid;
                    unsigned bb[2];
                    bb[0] = *(const unsigned*)&xs[b][n][kl];
                    bb[1] = *(const unsigned*)&xs[b][n][kl + 8];
#pragma unroll
                    for (int f = 0; f < 3; f++) mma16816(acc[f][g], a[f], bb);
                }
            }
            __syncthreads();
            t = tn; iter++;
        }
    }
#pragma unroll
    for (int f = 0; f < 3; f++) {
        int m = m0 + f * 16 + gid;
#pragma unroll
        for (int g = 0; g < 12; g++) {
            int n = n0 + g * 8 + 2 * tig;
            atomicAdd(&g_G[m * CC + n],           acc[f][g][0]);
            atomicAdd(&g_G[m * CC + n + 1],       acc[f][g][1]);
            atomicAdd(&g_G[(m + 8) * CC + n],     acc[f][g][2]);
            atomicAdd(&g_G[(m + 8) * CC + n + 1], acc[f][g][3]);
        }
    }
#pragma unroll
    for (int i = 0; i < 12; i++) atomicAdd(&g_s[(tid + 256 * i) >> 4], srow[i]);
}

// ---------------- T = W_{q,k} @ G ; u = W_{q,k} @ s ----------------
__global__ void k_T() {
    int o = blockIdx.x, j = threadIdx.x;
    float acc = 0.f;
#pragma unroll 4
    for (int c = 0; c < CC; c++) acc += g_Wf[o * CC + c] * g_G[c * CC + j];
    g_T[o * CC + j] = acc;
    __shared__ float sh[CC];
    sh[j] = g_Wf[o * CC + j] * g_s[j];
    __syncthreads();
    if (j < 64) sh[j] += sh[j + 64] + sh[j + 128];
    __syncthreads();
    if (j < 32) {
        float a = sh[j] + sh[j + 32];
#pragma unroll
        for (int off = 16; off > 0; off >>= 1) a += __shfl_down_sync(0xffffffffu, a, off);
        if (j == 0) g_u[o] = a;
    }
}

// ---------------- attn -> mn -> gating -> gm (compact bf16) ----------------
__global__ __launch_bounds__(1024) void k_gm(const float* __restrict__ mn_w,
                                             const float* __restrict__ gating) {
    int h = blockIdx.x, tid = threadIdx.x;
    int d = tid >> 5, e = tid & 31;
    __shared__ float attn[32][33];
    __shared__ float nq[32], nk[32];
    if (tid < 64) {
        int o = (tid < 32) ? (h * 32 + tid) : (CC + h * 32 + (tid - 32));
        float acc = 0.f;
        for (int c2 = 0; c2 < CC; c2++) acc += g_T[o * CC + c2] * g_Wf[o * CC + c2];
        float b = g_bias[o];
        acc += 2.f * b * g_u[o] + (float)HW * b * b;
        float nval = fmaxf(sqrtf(fmaxf(acc, 0.f)), 1e-12f);
        if (tid < 32) nq[tid] = nval; else nk[tid - 32] = nval;
    }
    __syncthreads();
    int oq = h * 32 + d, ok = CC + h * 32 + e;
    float acc = 0.f;
    for (int c2 = 0; c2 < CC; c2++) acc += g_T[oq * CC + c2] * g_Wf[ok * CC + c2];
    acc += g_bias[ok] * g_u[oq] + g_bias[oq] * g_u[ok] + (float)HW * g_bias[oq] * g_bias[ok];
    attn[d][e] = acc / (nq[d] * nk[e]);
    __syncthreads();
    float g1 = gating[h], g2 = gating[NHEAD + h];
    float acc2 = 0.f;
#pragma unroll
    for (int e2 = 0; e2 < 32; e2++)
        acc2 += attn[d][e2] * (g1 * mn_w[e * 32 + e2] + g2 * mn_w[(32 + e) * 32 + e2]);
    g_gmc[(h * 32 + d) * 32 + e] = __float2bfloat16(acc2);
}

// ---------------- fused kernel: 192x64 tiles, register-domain softmax -----------
// smem: XH[64][200]bf16 @0, CD[64][200]bf16 @25600, SB[2][2][64][2]f32 @51200 = 53248 B
__global__ __launch_bounds__(256, 3) void k_fused(const float* __restrict__ x,
                                                  const float* __restrict__ cond,
                                                  float* __restrict__ out) {
    extern __shared__ __align__(16) char smr[];
    unsigned short* XH = (unsigned short*)(smr);
    unsigned short* CD = (unsigned short*)(smr + 25600);
    float* SB = (float*)(smr + 51200);
    int tid = threadIdx.x;
    int p0 = blockIdx.x * 64;
    int warp = tid >> 5, lane = tid & 31, gid = lane >> 2, tig = lane & 3;
    int aidx = warp >> 1, par = warp & 1;
    int m0 = aidx * 48, n0 = par * 32;

    // ---- stage xhat (bf16) and cond (bf16), pixel-major [n][c] ----
#pragma unroll
    for (int q = tid; q < 1536; q += 256) {
        int c  = (q >> 4) * 2;
        int n4 = (q & 15) * 4;
        float4 mu4 = *(const float4*)(g_mu + p0 + n4);
        float4 rs4 = *(const float4*)(g_rstd + p0 + n4);
        float4 xa = *(const float4*)(x + c * HW + p0 + n4);
        float4 xb = *(const float4*)(x + (c + 1) * HW + p0 + n4);
        float4 ca = *(const float4*)(cond + c * HW + p0 + n4);
        float4 cb = *(const float4*)(cond + (c + 1) * HW + p0 + n4);
        float mus[4] = {mu4.x, mu4.y, mu4.z, mu4.w};
        float rss[4] = {rs4.x, rs4.y, rs4.z, rs4.w};
        float xas[4] = {xa.x, xa.y, xa.z, xa.w};
        float xbs[4] = {xb.x, xb.y, xb.z, xb.w};
        float cas[4] = {ca.x, ca.y, ca.z, ca.w};
        float cbs[4] = {cb.x, cb.y, cb.z, cb.w};
#pragma unroll
        for (int j = 0; j < 4; j++) {
            __nv_bfloat162 hx = __floats2bfloat162_rn((xas[j] - mus[j]) * rss[j],
                                                      (xbs[j] - mus[j]) * rss[j]);
            *(unsigned*)&XH[(n4 + j) * 200 + c] = *(unsigned*)&hx;
            __nv_bfloat162 hc = __floats2bfloat162_rn(cas[j], cbs[j]);
            *(unsigned*)&CD[(n4 + j) * 200 + c] = *(unsigned*)&hc;
        }
    }
    __syncthreads();

    // ---- GEMM1: v = Wv @ xhat (accv in regs) ----
    float accv[3][4][4];
#pragma unroll
    for (int f = 0; f < 3; f++)
#pragma unroll
        for (int g = 0; g < 4; g++)
#pragma unroll
            for (int r = 0; r < 4; r++) accv[f][g][r] = 0.f;
#pragma unroll
    for (int kk = 0; kk < CC; kk += 32) {
#pragma unroll
        for (int ks = 0; ks < 2; ks++) {
            int kl = ks * 16 + 2 * tig;
            unsigned a[3][4];
#pragma unroll
            for (int f = 0; f < 3; f++) {
                int r = m0 + f * 16 + gid;
                a[f][0] = *(const unsigned*)&g_Wvb[r * CC + kk + kl];
                a[f][1] = *(const unsigned*)&g_Wvb[(r + 8) * CC + kk + kl];
                a[f][2] = *(const unsigned*)&g_Wvb[r * CC + kk + kl + 8];
                a[f][3] = *(const unsigned*)&g_Wvb[(r + 8) * CC + kk + kl + 8];
            }
#pragma unroll
            for (int g = 0; g < 4; g++) {
                int n = n0 + g * 8 + gid;
                unsigned bb[2];
                bb[0] = *(const unsigned*)&XH[n * 200 + kk + kl];
                bb[1] = *(const unsigned*)&XH[n * 200 + kk + kl + 8];
#pragma unroll
                for (int f = 0; f < 3; f++) mma16816(accv[f][g], a[f], bb);
            }
        }
    }

    // ---- GEMM2 (f-wise, block-diag gm): t = mi * (v + bias), folded into accv ----
#pragma unroll
    for (int f = 0; f < 3; f++) {
        float accm[4][4];
#pragma unroll
        for (int g = 0; g < 4; g++)
#pragma unroll
            for (int r = 0; r < 4; r++) accm[g][r] = 0.f;
        int row16 = m0 + f * 16;
        int kkf = (row16 >> 5) << 5;
#pragma unroll
        for (int ks = 0; ks < 2; ks++) {
            int kl = ks * 16 + 2 * tig;
            unsigned a[4];
            int r = row16 + gid;
            a[0] = *(const unsigned*)&g_gmc[r * 32 + kl];
            a[1] = *(const unsigned*)&g_gmc[(r + 8) * 32 + kl];
            a[2] = *(const unsigned*)&g_gmc[r * 32 + kl + 8];
            a[3] = *(const unsigned*)&g_gmc[(r + 8) * 32 + kl + 8];
#pragma unroll
            for (int g = 0; g < 4; g++) {
                int n = n0 + g * 8 + gid;
                unsigned bb[2];
                bb[0] = *(const unsigned*)&CD[n * 200 + kkf + kl];
                bb[1] = *(const unsigned*)&CD[n * 200 + kkf + kl + 8];
                mma16816(accm[g], a, bb);
            }
        }
        float bv0 = g_bias[384 + row16 + gid];
        float bv1 = g_bias[384 + row16 + gid + 8];
#pragma unroll
        for (int g = 0; g < 4; g++) {
            accv[f][g][0] = accm[g][0] * (accv[f][g][0] + bv0);
            accv[f][g][1] = accm[g][1] * (accv[f][g][1] + bv0);
            accv[f][g][2] = accm[g][2] * (accv[f][g][2] + bv1);
            accv[f][g][3] = accm[g][3] * (accv[f][g][3] + bv1);
        }
    }

    // ---- register-domain softmax over head-dim ----
    // even aidx: (f0,f1) full head, f2 = straddle lower half
    // odd  aidx: f0 = straddle upper half, (f1,f2) full head
    int fa = (aidx & 1) ? 1 : 0;
    int fb = fa + 1;
    int fs = (aidx & 1) ? 0 : 2;
    int hs = aidx >> 1;                 // straddle-head slot (0 or 1)
    int side = aidx & 1;                // 0 = lower rows, 1 = upper rows
    float* SBme = SB + ((hs * 2 + side) * 64) * 2;
    float* SBot = SB + ((hs * 2 + (side ^ 1)) * 64) * 2;

    // full head: complete softmax in registers
#pragma unroll
    for (int g = 0; g < 4; g++) {
#pragma unroll
        for (int e = 0; e < 2; e++) {
            float v0 = accv[fa][g][e], v1 = accv[fa][g][e + 2];
            float w0 = accv[fb][g][e], w1 = accv[fb][g][e + 2];
            float m = redmax(fmaxf(fmaxf(v0, v1), fmaxf(w0, w1)));
            v0 = __expf(v0 - m); v1 = __expf(v1 - m);
            w0 = __expf(w0 - m); w1 = __expf(w1 - m);
            float inv = 1.f / redsum(v0 + v1 + w0 + w1);
            accv[fa][g][e] = v0 * inv; accv[fa][g][e + 2] = v1 * inv;
            accv[fb][g][e] = w0 * inv; accv[fb][g][e + 2] = w1 * inv;
        }
    }
    // straddle head: local partials + publish
    float msv[8], ssv[8];
#pragma unroll
    for (int g = 0; g < 4; g++) {
#pragma unroll
        for (int e = 0; e < 2; e++) {
            int idx = g * 2 + e;
            float v0 = accv[fs][g][e], v1 = accv[fs][g][e + 2];
            float m = redmax(fmaxf(v0, v1));
            v0 = __expf(v0 - m); v1 = __expf(v1 - m);
            float s = redsum(v0 + v1);
            accv[fs][g][e] = v0; accv[fs][g][e + 2] = v1;
            msv[idx] = m; ssv[idx] = s;
            if (gid == 0) {
                int n = n0 + g * 8 + 2 * tig + e;
                SBme[n * 2]     = m;
                SBme[n * 2 + 1] = s;
            }
        }
    }
    __syncthreads();   // SB visible; all XH/CD reads complete
    // straddle finalize
#pragma unroll
    for (int g = 0; g < 4; g++) {
#pragma unroll
        for (int e = 0; e < 2; e++) {
            int idx = g * 2 + e;
            int n = n0 + g * 8 + 2 * tig + e;
            float mo = SBot[n * 2], so = SBot[n * 2 + 1];
            float M = fmaxf(msv[idx], mo);
            float S = ssv[idx] * __expf(msv[idx] - M) + so * __expf(mo - M);
            float scale = __expf(msv[idx] - M) / S;
            accv[fs][g][e]     *= scale;
            accv[fs][g][e + 2] *= scale;
        }
    }
    // write probs (bf16) into XH [n][c]
#pragma unroll
    for (int f = 0; f < 3; f++) {
        int r0 = m0 + f * 16 + gid;
#pragma unroll
        for (int g = 0; g < 4; g++) {
            int n = n0 + g * 8 + 2 * tig;
            __nv_bfloat16 b00 = __float2bfloat16(accv[f][g][0]);
            __nv_bfloat16 b01 = __float2bfloat16(accv[f][g][1]);
            __nv_bfloat16 b10 = __float2bfloat16(accv[f][g][2]);
            __nv_bfloat16 b11 = __float2bfloat16(accv[f][g][3]);
            XH[n * 200 + r0]           = *(unsigned short*)&b00;
            XH[(n + 1) * 200 + r0]     = *(unsigned short*)&b01;
            XH[n * 200 + r0 + 8]       = *(unsigned short*)&b10;
            XH[(n + 1) * 200 + r0 + 8] = *(unsigned short*)&b11;
        }
    }
    __syncthreads();   // probs visible

    // ---- GEMM3: out = proj @ probs + x ----
    float acc[3][4][4];
#pragma unroll
    for (int f = 0; f < 3; f++)
#pragma unroll
        for (int g = 0; g < 4; g++)
#pragma unroll
            for (int r = 0; r < 4; r++) acc[f][g][r] = 0.f;
#pragma unroll
    for (int kk = 0; kk < CC; kk += 32) {
#pragma unroll
        for (int ks = 0; ks < 2; ks++) {
            int kl = ks * 16 + 2 * tig;
            unsigned a[3][4];
#pragma unroll
            for (int f = 0; f < 3; f++) {
                int r = m0 + f * 16 + gid;
                a[f][0] = *(const unsigned*)&g_Wpb[r * CC + kk + kl];
                a[f][1] = *(const unsigned*)&g_Wpb[(r + 8) * CC + kk + kl];
                a[f][2] = *(const unsigned*)&g_Wpb[r * CC + kk + kl + 8];
                a[f][3] = *(const unsigned*)&g_Wpb[(r + 8) * CC + kk + kl + 8];
            }
#pragma unroll
            for (int g = 0; g < 4; g++) {
                int n = n0 + g * 8 + gid;
                unsigned bb[2];
                bb[0] = *(const unsigned*)&XH[n * 200 + kk + kl];
                bb[1] = *(const unsigned*)&XH[n * 200 + kk + kl + 8];
#pragma unroll
                for (int f = 0; f < 3; f++) mma16816(acc[f][g], a[f], bb);
            }
        }
    }
#pragma unroll
    for (int f = 0; f < 3; f++) {
        int m = m0 + f * 16 + gid;
#pragma unroll
        for (int g = 0; g < 4; g++) {
            int n = n0 + g * 8 + 2 * tig;
            float2 r0 = *(const float2*)(x + m * HW + p0 + n);
            float2 r1 = *(const float2*)(x + (m + 8) * HW + p0 + n);
            float2 o0 = make_float2(acc[f][g][0] + r0.x, acc[f][g][1] + r0.y);
            float2 o1 = make_float2(acc[f][g][2] + r1.x, acc[f][g][3] + r1.y);
            *(float2*)(out + m * HW + p0 + n) = o0;
            *(float2*)(out + (m + 8) * HW + p0 + n) = o1;
        }
    }
}

// ---------------- launch ----------------
extern "C" void kernel_launch(void* const* d_in, const int* in_sizes, int n_in,
                              void* d_out, int out_size) {
    const float* x      = (const float*)d_in[0];
    const float* cond   = (const float*)d_in[1];
    const float* ln_g   = (const float*)d_in[2];
    const float* ln_b   = (const float*)d_in[3];
    const float* pre_w  = (const float*)d_in[4];
    const float* pre_b  = (const float*)d_in[5];
    const float* qkv_w  = (const float*)d_in[6];
    const float* mn_w   = (const float*)d_in[7];
    const float* gating = (const float*)d_in[8];
    const float* proj_w = (const float*)d_in[9];
    float* out = (float*)d_out;

    cudaFuncSetAttribute(k_fused, cudaFuncAttributeMaxDynamicSharedMemorySize, 53248);

    k_zero<<<144, 256>>>();
    k_stats<<<HW / 256, 256>>>(x);
    k_fold<<<576, CC>>>(qkv_w, pre_w, ln_g, ln_b, pre_b);
    k_cvt<<<144, 256>>>(proj_w);
    k_gram<<<152, 256>>>(x);
    k_T<<<384, CC>>>();
    k_gm<<<NHEAD, 1024>>>(mn_w, gating);
    k_fused<<<HW / 64, 256, 53248>>>(x, cond, out);
}